// round 2
// baseline (speedup 1.0000x reference)
#include <cuda_runtime.h>

// C[b,g] = softor_s( softand_l( x[b, I[g,s,l]] ) ),  gamma = 1e-3
// B=64, G=2048, S=32, L=8
// softand = min - gamma*ln(sum exp((min-v)/gamma))   (stable LSE)
// softor  = max + gamma*ln(sum exp((a-max)/gamma))

#define NB 64
#define NG 2048
#define NS 32
#define NL 8

// Transposed x: xT[g][b] so the 64 b-values for one gathered index are
// contiguous -> warp lanes map to b -> fully coalesced 128B gathers.
__device__ float g_xT[NG * NB];  // 512 KB device-global scratch (allowed)

__global__ void transpose_kernel(const float* __restrict__ x) {
    int t = blockIdx.x * blockDim.x + threadIdx.x;  // t = b*NG + g (coalesced read)
    if (t < NB * NG) {
        int b = t >> 11;          // / NG
        int g = t & (NG - 1);     // % NG
        g_xT[g * NB + b] = x[t];
    }
}

__device__ __forceinline__ float ex2_approx(float t) {
    float r;
    asm("ex2.approx.ftz.f32 %0, %1;" : "=f"(r) : "f"(t));
    return r;
}
__device__ __forceinline__ float lg2_approx(float t) {
    float r;
    asm("lg2.approx.f32 %0, %1;" : "=f"(r) : "f"(t));
    return r;
}

// One block per g, 64 threads = 64 batch rows. Indices are warp-uniform
// (LDS broadcast); gathers are coalesced via xT.
__global__ __launch_bounds__(NB) void clause_kernel(
    const int* __restrict__ I,  // [NG, NS, NL] int32
    float* __restrict__ out)    // [NB, NG]
{
    const int g = blockIdx.x;
    const int b = threadIdx.x;

    __shared__ int sidx[NS * NL];
    for (int i = threadIdx.x; i < NS * NL; i += NB)
        sidx[i] = I[g * (NS * NL) + i] & (NG - 1);  // mask: safety, no-op for valid data
    __syncthreads();

    // 1/(gamma*ln2) and gamma*ln2
    const float KINV = 1442.6950408889634f;
    const float GLN2 = 0.0006931471805599453f;

    float a[NS];

#pragma unroll
    for (int s = 0; s < NS; s++) {
        float v[NL];
#pragma unroll
        for (int l = 0; l < NL; l++) {
            int idx = sidx[s * NL + l];
            v[l] = g_xT[idx * NB + b];
        }
        float m = v[0];
#pragma unroll
        for (int l = 1; l < NL; l++) m = fminf(m, v[l]);
        float sum = 0.0f;
#pragma unroll
        for (int l = 0; l < NL; l++) {
            // (m - v) <= 0; argument in [-1442, 0]; ex2.approx.ftz -> +0 on deep underflow
            sum += ex2_approx((m - v[l]) * KINV);
        }
        a[s] = m - GLN2 * lg2_approx(sum);
    }

    float M = a[0];
#pragma unroll
    for (int s = 1; s < NS; s++) M = fmaxf(M, a[s]);
    float sum2 = 0.0f;
#pragma unroll
    for (int s = 0; s < NS; s++) {
        sum2 += ex2_approx((a[s] - M) * KINV);
    }
    float c = M + GLN2 * lg2_approx(sum2);

    out[b * NG + g] = c;
}

extern "C" void kernel_launch(void* const* d_in, const int* in_sizes, int n_in,
                              void* d_out, int out_size) {
    // Identify inputs by element count (robust to ordering):
    //   x:  64*2048   = 131072 float32
    //   I:  2048*32*8 = 524288 int32
    const float* x = nullptr;
    const int* I = nullptr;
    for (int i = 0; i < n_in; i++) {
        if (in_sizes[i] == NB * NG)           x = (const float*)d_in[i];
        else if (in_sizes[i] == NG * NS * NL) I = (const int*)d_in[i];
    }

    float* out = (float*)d_out;  // [64, 2048] fp32

    transpose_kernel<<<(NB * NG + 255) / 256, 256>>>(x);
    clause_kernel<<<NG, NB>>>(I, out);
}

// round 3
// speedup vs baseline: 1.2162x; 1.2162x over previous
#include <cuda_runtime.h>

// C[b,g] = softor_s( softand_l( x[b, I[g,s,l]] ) ),  gamma = 1e-3
// B=64, G=2048, S=32, L=8
// softand = min - gamma*ln(sum exp((min-v)/gamma))   (stable LSE)
// softor  = max + gamma*ln(sum exp((a-max)/gamma))

#define NB 64
#define NG 2048
#define NS 32
#define NL 8
#define NCHUNK 4              // s-dimension split across 4 warps
#define SPER (NS / NCHUNK)    // 8 s-values per chunk

// Transposed x: xT[g][b] so the 64 b-values for one gathered index are
// contiguous -> warp lanes (float2 each) -> fully coalesced gathers.
__device__ float g_xT[NG * NB];

__global__ void transpose_kernel(const float* __restrict__ x) {
    int t = blockIdx.x * blockDim.x + threadIdx.x;  // t = b*NG + g (coalesced read)
    if (t < NB * NG) {
        int b = t >> 11;          // / NG
        int g = t & (NG - 1);     // % NG
        g_xT[g * NB + b] = x[t];
    }
}

__device__ __forceinline__ float ex2_approx(float t) {
    float r;
    asm("ex2.approx.ftz.f32 %0, %1;" : "=f"(r) : "f"(t));
    return r;
}
__device__ __forceinline__ float lg2_approx(float t) {
    float r;
    asm("lg2.approx.f32 %0, %1;" : "=f"(r) : "f"(t));
    return r;
}

// 1/(gamma*ln2) and gamma*ln2
#define KINV 1442.6950408889634f
#define GLN2 0.0006931471805599453f

// One block (128 threads) per g:
//   warp w (=chunk) handles s in [w*8, w*8+8); lane covers b = 2*lane, 2*lane+1.
// Partial softor state (max, sum-of-exp) merged across the 4 chunks in smem.
__global__ __launch_bounds__(NCHUNK * 32) void clause_kernel(
    const int* __restrict__ I,  // [NG, NS, NL] int32
    float* __restrict__ out)    // [NB, NG]
{
    const int g = blockIdx.x;
    const int tid = threadIdx.x;
    const int lane = tid & 31;
    const int chunk = tid >> 5;

    __shared__ int sidx[NS * NL];
    __shared__ float pM[NCHUNK][NB];
    __shared__ float pS[NCHUNK][NB];

    for (int i = tid; i < NS * NL; i += NCHUNK * 32)
        sidx[i] = I[g * (NS * NL) + i] & (NG - 1);
    __syncthreads();

    const int b0 = lane * 2;
    const float2* __restrict__ xT2 =
        (const float2*)(g_xT);  // row stride NB/2 float2

    float ax[SPER], ay[SPER];

#pragma unroll
    for (int si = 0; si < SPER; si++) {
        const int s = chunk * SPER + si;
        float2 v[NL];
#pragma unroll
        for (int l = 0; l < NL; l++) {
            int idx = sidx[s * NL + l];
            v[l] = xT2[idx * (NB / 2) + lane];
        }
        float mx = v[0].x, my = v[0].y;
#pragma unroll
        for (int l = 1; l < NL; l++) {
            mx = fminf(mx, v[l].x);
            my = fminf(my, v[l].y);
        }
        float sx = 0.0f, sy = 0.0f;
#pragma unroll
        for (int l = 0; l < NL; l++) {
            sx += ex2_approx((mx - v[l].x) * KINV);
            sy += ex2_approx((my - v[l].y) * KINV);
        }
        ax[si] = mx - GLN2 * lg2_approx(sx);
        ay[si] = my - GLN2 * lg2_approx(sy);
    }

    // Partial softor over this chunk's 8 s-values
    float Mx = ax[0], My = ay[0];
#pragma unroll
    for (int si = 1; si < SPER; si++) {
        Mx = fmaxf(Mx, ax[si]);
        My = fmaxf(My, ay[si]);
    }
    float Sx = 0.0f, Sy = 0.0f;
#pragma unroll
    for (int si = 0; si < SPER; si++) {
        Sx += ex2_approx((ax[si] - Mx) * KINV);
        Sy += ex2_approx((ay[si] - My) * KINV);
    }

    pM[chunk][b0] = Mx;  pM[chunk][b0 + 1] = My;
    pS[chunk][b0] = Sx;  pS[chunk][b0 + 1] = Sy;
    __syncthreads();

    // First 64 threads: merge 4 partial (M, S) pairs per b and write out.
    if (tid < NB) {
        const int b = tid;
        float M = pM[0][b];
#pragma unroll
        for (int c = 1; c < NCHUNK; c++) M = fmaxf(M, pM[c][b]);
        float S = 0.0f;
#pragma unroll
        for (int c = 0; c < NCHUNK; c++)
            S += pS[c][b] * ex2_approx((pM[c][b] - M) * KINV);
        out[b * NG + g] = M + GLN2 * lg2_approx(S);
    }
}

extern "C" void kernel_launch(void* const* d_in, const int* in_sizes, int n_in,
                              void* d_out, int out_size) {
    // Identify inputs by element count:
    //   x:  64*2048   = 131072 float32
    //   I:  2048*32*8 = 524288 int32
    const float* x = nullptr;
    const int* I = nullptr;
    for (int i = 0; i < n_in; i++) {
        if (in_sizes[i] == NB * NG)           x = (const float*)d_in[i];
        else if (in_sizes[i] == NG * NS * NL) I = (const int*)d_in[i];
    }

    float* out = (float*)d_out;  // [64, 2048] fp32

    transpose_kernel<<<(NB * NG + 255) / 256, 256>>>(x);
    clause_kernel<<<NG, NCHUNK * 32>>>(I, out);
}

// round 4
// speedup vs baseline: 1.2392x; 1.0189x over previous
#include <cuda_runtime.h>

// C[b,g] = softor_s( softand_l( x[b, I[g,s,l]] ) ),  gamma = 1e-3
// B=64, G=2048, S=32, L=8

#define NB 64
#define NG 2048
#define NS 32
#define NL 8
#define NCHUNK 4              // s-dimension split across 4 warps
#define SPER (NS / NCHUNK)    // 8 s-values per chunk

// 1/(gamma*ln2) and gamma*ln2
#define KINV 1442.6950408889634f
#define GLN2 0.0006931471805599453f

// Transposed x: xT[g][b] so the 64 b-values for one gathered index are
// contiguous -> warp lanes (float2 each) -> fully coalesced gathers.
__device__ float g_xT[NG * NB];

// Tiled transpose: 64x2048 -> 2048x64, coalesced reads AND writes.
// grid(64,2), block(32,8). Tile = 32g x 32b.
__global__ void transpose_kernel(const float* __restrict__ x) {
    __shared__ float tile[32][33];
    const int gx = blockIdx.x * 32;
    const int bx = blockIdx.y * 32;
    const int tx = threadIdx.x;
    const int ty = threadIdx.y;
#pragma unroll
    for (int i = 0; i < 32; i += 8)
        tile[ty + i][tx] = x[(bx + ty + i) * NG + gx + tx];  // consecutive g: coalesced
    __syncthreads();
#pragma unroll
    for (int i = 0; i < 32; i += 8)
        g_xT[(gx + ty + i) * NB + bx + tx] = tile[tx][ty + i];  // consecutive b: coalesced
}

__device__ __forceinline__ float ex2_approx(float t) {
    float r;
    asm("ex2.approx.ftz.f32 %0, %1;" : "=f"(r) : "f"(t));
    return r;
}
__device__ __forceinline__ float lg2_approx(float t) {
    float r;
    asm("lg2.approx.f32 %0, %1;" : "=f"(r) : "f"(t));
    return r;
}

// One block (128 threads) per g:
//   warp w handles s in [w*8, w*8+8); lane covers b = 2*lane, 2*lane+1 (float2).
// Softor LSE state kept ONLINE (M,S) to avoid register arrays.
__global__ __launch_bounds__(NCHUNK * 32, 14) void clause_kernel(
    const int* __restrict__ I,  // [NG, NS, NL] int32
    float* __restrict__ out)    // [NB, NG]
{
    const int g = blockIdx.x;
    const int tid = threadIdx.x;
    const int lane = tid & 31;
    const int chunk = tid >> 5;

    __shared__ int sidx[NS * NL];
    __shared__ float pM[NCHUNK][NB];
    __shared__ float pS[NCHUNK][NB];

    for (int i = tid; i < NS * NL; i += NCHUNK * 32)
        sidx[i] = I[g * (NS * NL) + i] & (NG - 1);
    __syncthreads();

    const float2* __restrict__ xT2 = (const float2*)(g_xT);  // row stride NB/2
    const int4* __restrict__ sidx4 = (const int4*)sidx;

    // Online softor state
    float Mx = -1e30f, My = -1e30f;
    float Sx = 0.0f, Sy = 0.0f;

#pragma unroll
    for (int si = 0; si < SPER; si++) {
        const int s = chunk * SPER + si;
        const int4 i0 = sidx4[s * 2 + 0];
        const int4 i1 = sidx4[s * 2 + 1];

        float2 v0 = xT2[i0.x * (NB / 2) + lane];
        float2 v1 = xT2[i0.y * (NB / 2) + lane];
        float2 v2 = xT2[i0.z * (NB / 2) + lane];
        float2 v3 = xT2[i0.w * (NB / 2) + lane];
        float2 v4 = xT2[i1.x * (NB / 2) + lane];
        float2 v5 = xT2[i1.y * (NB / 2) + lane];
        float2 v6 = xT2[i1.z * (NB / 2) + lane];
        float2 v7 = xT2[i1.w * (NB / 2) + lane];

        float mx = fminf(fminf(fminf(v0.x, v1.x), fminf(v2.x, v3.x)),
                         fminf(fminf(v4.x, v5.x), fminf(v6.x, v7.x)));
        float my = fminf(fminf(fminf(v0.y, v1.y), fminf(v2.y, v3.y)),
                         fminf(fminf(v4.y, v5.y), fminf(v6.y, v7.y)));

        float sx = ex2_approx((mx - v0.x) * KINV) + ex2_approx((mx - v1.x) * KINV)
                 + ex2_approx((mx - v2.x) * KINV) + ex2_approx((mx - v3.x) * KINV)
                 + ex2_approx((mx - v4.x) * KINV) + ex2_approx((mx - v5.x) * KINV)
                 + ex2_approx((mx - v6.x) * KINV) + ex2_approx((mx - v7.x) * KINV);
        float sy = ex2_approx((my - v0.y) * KINV) + ex2_approx((my - v1.y) * KINV)
                 + ex2_approx((my - v2.y) * KINV) + ex2_approx((my - v3.y) * KINV)
                 + ex2_approx((my - v4.y) * KINV) + ex2_approx((my - v5.y) * KINV)
                 + ex2_approx((my - v6.y) * KINV) + ex2_approx((my - v7.y) * KINV);

        float a_x = mx - GLN2 * lg2_approx(sx);
        float a_y = my - GLN2 * lg2_approx(sy);

        // Online LSE merge (softor): M' = max(M, a); S = S*2^((M-M')k) + 2^((a-M')k)
        float nMx = fmaxf(Mx, a_x);
        Sx = Sx * ex2_approx((Mx - nMx) * KINV) + ex2_approx((a_x - nMx) * KINV);
        Mx = nMx;
        float nMy = fmaxf(My, a_y);
        Sy = Sy * ex2_approx((My - nMy) * KINV) + ex2_approx((a_y - nMy) * KINV);
        My = nMy;
    }

    const int b0 = lane * 2;
    pM[chunk][b0] = Mx;  pM[chunk][b0 + 1] = My;
    pS[chunk][b0] = Sx;  pS[chunk][b0 + 1] = Sy;
    __syncthreads();

    // First 64 threads: merge NCHUNK partial (M, S) pairs per b and write out.
    if (tid < NB) {
        const int b = tid;
        float M = pM[0][b];
#pragma unroll
        for (int c = 1; c < NCHUNK; c++) M = fmaxf(M, pM[c][b]);
        float S = 0.0f;
#pragma unroll
        for (int c = 0; c < NCHUNK; c++)
            S += pS[c][b] * ex2_approx((pM[c][b] - M) * KINV);
        out[b * NG + g] = M + GLN2 * lg2_approx(S);
    }
}

extern "C" void kernel_launch(void* const* d_in, const int* in_sizes, int n_in,
                              void* d_out, int out_size) {
    // Identify inputs by element count:
    //   x:  64*2048   = 131072 float32
    //   I:  2048*32*8 = 524288 int32
    const float* x = nullptr;
    const int* I = nullptr;
    for (int i = 0; i < n_in; i++) {
        if (in_sizes[i] == NB * NG)           x = (const float*)d_in[i];
        else if (in_sizes[i] == NG * NS * NL) I = (const int*)d_in[i];
    }

    float* out = (float*)d_out;  // [64, 2048] fp32

    dim3 tgrid(NG / 32, NB / 32);
    dim3 tblock(32, 8);
    transpose_kernel<<<tgrid, tblock>>>(x);
    clause_kernel<<<NG, NCHUNK * 32>>>(I, out);
}